// round 2
// baseline (speedup 1.0000x reference)
#include <cuda_runtime.h>
#include <cstdint>

// ---------------------------------------------------------------------------
// PureCartesianTensorProductO3: out[n,:] = sum over 15 paths x 4 parity combos
//   of  W_p[Z,a,b] * spatial_contract( t1[n,s1,L1,a,:], t2[n,s2,L2,b,:] )
// Layout per row (832 floats): s in {0,1} blocks of 416; within block
//   L0 at [0,32), L1 at [32,128), L2 at [128,416); element (c, spatial) at
//   c*3^L + lin(spatial).
// ---------------------------------------------------------------------------

#define NROWS   8192
#define FEAT    832
#define SBLK    416
#define TILE    16
#define NTHREADS 128

// path tables (compile-time)
__host__ __device__ constexpr int kP3[3]   = {1, 3, 9};
__host__ __device__ constexpr int kLOFF[3] = {0, 32, 128};
__host__ __device__ constexpr int kL1[15] = {0,0,0,1,1,1,1,1,1,2,2,2,2,2,2};
__host__ __device__ constexpr int kL2[15] = {0,1,2,0,1,1,1,2,2,0,1,1,2,2,2};
__host__ __device__ constexpr int kLO[15] = {0,1,2,1,2,0,1,1,2,2,1,2,2,0,1};
__host__ __device__ constexpr int kUE[15] = {0,0,0,0,0,0,1,0,1,0,0,1,0,0,1};

// SMEM carve (floats)
#define SX_STRIDE 833
#define SX_FLOATS (TILE * SX_STRIDE)              // 13328
#define SB_FLOATS (32 * 4 * 9 * TILE)             // 18432
#define SW_STRIDE 34
#define SW_FLOATS (128 * SW_STRIDE)               // 4352
#define SMEM_FLOATS (2 * SX_FLOATS + SB_FLOATS + SW_FLOATS)
#define SMEM_BYTES (SMEM_FLOATS * 4)              // 197760 B

typedef unsigned long long u64;

__device__ __forceinline__ u64 pk2(float x, float y) {
    u64 r; asm("mov.b64 %0, {%1, %2};" : "=l"(r) : "f"(x), "f"(y)); return r;
}
__device__ __forceinline__ void upk2(u64 v, float& x, float& y) {
    asm("mov.b64 {%0, %1}, %2;" : "=f"(x), "=f"(y) : "l"(v));
}
// packed 2x fp32 FMA (PTX-only on sm_103a; doubles FFMA throughput vs 3-reg FFMA)
__device__ __forceinline__ void ffma2(u64& d, u64 a, u64 b) {
    asm("fma.rn.f32x2 %0, %1, %2, %0;" : "+l"(d) : "l"(a), "l"(b));
}

__device__ __forceinline__ float dot3(const float* __restrict__ u, const float* __restrict__ v) {
    return fmaf(u[0], v[0], fmaf(u[1], v[1], u[2] * v[2]));
}
__device__ __forceinline__ void cross3(const float* __restrict__ u, const float* __restrict__ v,
                                       float* __restrict__ o) {
    o[0] = u[1] * v[2] - u[2] * v[1];
    o[1] = u[2] * v[0] - u[0] * v[2];
    o[2] = u[0] * v[1] - u[1] * v[0];
}

// Spatial contraction per path: B[m] from t1 (3^L1 floats) and t2 (3^L2 floats)
template <int P>
__device__ __forceinline__ void compute_B(const float* __restrict__ t1,
                                          const float* __restrict__ t2,
                                          float* __restrict__ B) {
    if constexpr (P == 0) {                // (0,0)->0
        B[0] = t1[0] * t2[0];
    } else if constexpr (P == 1) {         // (0,1)->1
        #pragma unroll
        for (int m = 0; m < 3; ++m) B[m] = t1[0] * t2[m];
    } else if constexpr (P == 2) {         // (0,2)->2
        #pragma unroll
        for (int m = 0; m < 9; ++m) B[m] = t1[0] * t2[m];
    } else if constexpr (P == 3) {         // (1,0)->1
        #pragma unroll
        for (int m = 0; m < 3; ++m) B[m] = t1[m] * t2[0];
    } else if constexpr (P == 4) {         // (1,1) k=0 ->2 : B[3i+j]=t1[i]t2[j]
        #pragma unroll
        for (int i = 0; i < 3; ++i)
            #pragma unroll
            for (int j = 0; j < 3; ++j) B[3 * i + j] = t1[i] * t2[j];
    } else if constexpr (P == 5) {         // (1,1) k=1 ->0 : dot
        B[0] = dot3(t1, t2);
    } else if constexpr (P == 6) {         // (1,1) eps ->1 : cross
        cross3(t1, t2, B);
    } else if constexpr (P == 7) {         // (1,2) k=1 ->1 : B[d]=sum_c t1[c]t2[d,c]
        #pragma unroll
        for (int d = 0; d < 3; ++d) B[d] = dot3(t1, t2 + 3 * d);
    } else if constexpr (P == 8) {         // (1,2) eps ->2 : B[d,p]=eps[p,c,e]t1[c]t2[d,e]
        #pragma unroll
        for (int d = 0; d < 3; ++d) cross3(t1, t2 + 3 * d, B + 3 * d);
    } else if constexpr (P == 9) {         // (2,0)->2
        #pragma unroll
        for (int m = 0; m < 9; ++m) B[m] = t1[m] * t2[0];
    } else if constexpr (P == 10) {        // (2,1) k=1 ->1 : B[c]=sum_d t1[c,d]t2[d]
        #pragma unroll
        for (int c = 0; c < 3; ++c) B[c] = dot3(t1 + 3 * c, t2);
    } else if constexpr (P == 11) {        // (2,1) eps ->2 : B[c,p]=eps[p,d,e]t1[c,d]t2[e]
        #pragma unroll
        for (int c = 0; c < 3; ++c) cross3(t1 + 3 * c, t2, B + 3 * c);
    } else if constexpr (P == 12) {        // (2,2) k=1 ->2 : B[c,e]=sum_d t1[c,d]t2[e,d]
        #pragma unroll
        for (int c = 0; c < 3; ++c)
            #pragma unroll
            for (int e = 0; e < 3; ++e) B[3 * c + e] = dot3(t1 + 3 * c, t2 + 3 * e);
    } else if constexpr (P == 13) {        // (2,2) k=2 ->0 : full dot
        float s = 0.f;
        #pragma unroll
        for (int i = 0; i < 9; ++i) s = fmaf(t1[i], t2[i], s);
        B[0] = s;
    } else {                               // P==14 (2,2) eps ->1 : B[p]=eps[p,c,e] M[c,e]
        float M01 = dot3(t1 + 0, t2 + 3), M02 = dot3(t1 + 0, t2 + 6);
        float M10 = dot3(t1 + 3, t2 + 0), M12 = dot3(t1 + 3, t2 + 6);
        float M20 = dot3(t1 + 6, t2 + 0), M21 = dot3(t1 + 6, t2 + 3);
        B[0] = M12 - M21;
        B[1] = M20 - M02;
        B[2] = M01 - M10;
    }
}

template <int P>
__device__ __forceinline__ void process_path(const float* __restrict__ wgt,
                                             float* __restrict__ out,
                                             const float* __restrict__ sx1,
                                             const float* __restrict__ sx2,
                                             float* __restrict__ sB,
                                             float* __restrict__ sW,
                                             int row0, int tid) {
    constexpr int L1 = kL1[P], L2 = kL2[P], Lo = kLO[P], UE = kUE[P];
    constexpr int d1 = kP3[L1], d2 = kP3[L2], Mout = kP3[Lo];
    constexpr int O1 = kLOFF[L1], O2 = kLOFF[L2], Oo = kLOFF[Lo];

    const int zp = tid & 15;   // Z-pair index: handles Z = 2*zp, 2*zp+1
    const int rp = tid >> 4;   // row-pair index: rows 2*rp, 2*rp+1

    #pragma unroll 1
    for (int ss = 0; ss < 4; ++ss) {
        const int s1 = ss >> 1, s2 = ss & 1;
        const int so = s1 ^ s2 ^ UE;
        const float* wb = wgt + (size_t)(P * 4 + ss) * 32768;

        u64 acc0[Mout], acc1[Mout];
        #pragma unroll
        for (int m = 0; m < Mout; ++m) { acc0[m] = 0ull; acc1[m] = 0ull; }

        #pragma unroll 1
        for (int a0 = 0; a0 < 32; a0 += 4) {
            __syncthreads();  // previous GEMM done reading sB/sW
            // ---- stage W slice: W[Z, a0 + (rem>>5), rem&31] -> sW[rem*34 + Z]
            #pragma unroll
            for (int it = 0; it < 32; ++it) {
                int i = tid + it * NTHREADS;
                int Z = i >> 7, rem = i & 127;
                sW[rem * SW_STRIDE + Z] = wb[Z * 1024 + a0 * 32 + rem];
            }
            // ---- stage B: slot index MUST match GEMM's rem = ac*32 + b
            #pragma unroll
            for (int it = 0; it < 16; ++it) {
                int e = tid + it * NTHREADS;
                int r = e & 15, slot = e >> 4;       // slot in [0,128)
                int ac = slot >> 5, b = slot & 31;   // slot == ac*32 + b
                const float* t1 = sx1 + r * SX_STRIDE + s1 * SBLK + O1 + (a0 + ac) * d1;
                const float* t2 = sx2 + r * SX_STRIDE + s2 * SBLK + O2 + b * d2;
                float Bm[Mout];
                compute_B<P>(t1, t2, Bm);
                #pragma unroll
                for (int m = 0; m < Mout; ++m) sB[(slot * Mout + m) * TILE + r] = Bm[m];
            }
            __syncthreads();
            // ---- rank-128 update, packed f32x2 over the row pair
            #pragma unroll 2
            for (int b = 0; b < 32; ++b) {
                #pragma unroll
                for (int ac = 0; ac < 4; ++ac) {
                    const int rem = ac * 32 + b;
                    float2 w2 = *reinterpret_cast<const float2*>(sW + rem * SW_STRIDE + 2 * zp);
                    u64 wA = pk2(w2.x, w2.x);  // Z = 2*zp
                    u64 wB = pk2(w2.y, w2.y);  // Z = 2*zp+1
                    const float* bp = sB + (size_t)rem * Mout * TILE + 2 * rp;
                    #pragma unroll
                    for (int m = 0; m < Mout; ++m) {
                        u64 bv = *reinterpret_cast<const u64*>(bp + m * TILE);
                        ffma2(acc0[m], wA, bv);
                        ffma2(acc1[m], wB, bv);
                    }
                }
            }
        }
        // ---- flush (global RMW; rows exclusive per block, locations exclusive per thread)
        const int ob = so * SBLK + Oo;
        float* o0 = out + (size_t)(row0 + 2 * rp) * FEAT;
        float* o1 = o0 + FEAT;
        #pragma unroll
        for (int m = 0; m < Mout; ++m) {
            float v00, v01, v10, v11;
            upk2(acc0[m], v00, v01);
            upk2(acc1[m], v10, v11);
            o0[ob + (2 * zp) * Mout + m]     += v00;
            o1[ob + (2 * zp) * Mout + m]     += v01;
            o0[ob + (2 * zp + 1) * Mout + m] += v10;
            o1[ob + (2 * zp + 1) * Mout + m] += v11;
        }
    }
}

__global__ __launch_bounds__(NTHREADS)
void tp_o3_kernel(const float* __restrict__ x1, const float* __restrict__ x2,
                  const float* __restrict__ wgt, float* __restrict__ out) {
    extern __shared__ float sm[];
    float* sx1 = sm;
    float* sx2 = sx1 + SX_FLOATS;
    float* sB  = sx2 + SX_FLOATS;
    float* sW  = sB + SB_FLOATS;

    const int tid  = threadIdx.x;
    const int row0 = blockIdx.x * TILE;

    // stage input tiles (padded stride for conflict-free scalar reads)
    #pragma unroll 4
    for (int i = tid; i < TILE * FEAT; i += NTHREADS) {
        int r = i / FEAT, f = i - r * FEAT;
        sx1[r * SX_STRIDE + f] = x1[(size_t)(row0 + r) * FEAT + f];
        sx2[r * SX_STRIDE + f] = x2[(size_t)(row0 + r) * FEAT + f];
    }
    // (first __syncthreads inside each process_path chunk loop orders the fill)

    process_path<0>(wgt, out, sx1, sx2, sB, sW, row0, tid);
    process_path<1>(wgt, out, sx1, sx2, sB, sW, row0, tid);
    process_path<2>(wgt, out, sx1, sx2, sB, sW, row0, tid);
    process_path<3>(wgt, out, sx1, sx2, sB, sW, row0, tid);
    process_path<4>(wgt, out, sx1, sx2, sB, sW, row0, tid);
    process_path<5>(wgt, out, sx1, sx2, sB, sW, row0, tid);
    process_path<6>(wgt, out, sx1, sx2, sB, sW, row0, tid);
    process_path<7>(wgt, out, sx1, sx2, sB, sW, row0, tid);
    process_path<8>(wgt, out, sx1, sx2, sB, sW, row0, tid);
    process_path<9>(wgt, out, sx1, sx2, sB, sW, row0, tid);
    process_path<10>(wgt, out, sx1, sx2, sB, sW, row0, tid);
    process_path<11>(wgt, out, sx1, sx2, sB, sW, row0, tid);
    process_path<12>(wgt, out, sx1, sx2, sB, sW, row0, tid);
    process_path<13>(wgt, out, sx1, sx2, sB, sW, row0, tid);
    process_path<14>(wgt, out, sx1, sx2, sB, sW, row0, tid);
}

extern "C" void kernel_launch(void* const* d_in, const int* in_sizes, int n_in,
                              void* d_out, int out_size) {
    const float* x1  = (const float*)d_in[0];
    const float* x2  = (const float*)d_in[1];
    const float* wgt = (const float*)d_in[2];
    float* out = (float*)d_out;

    cudaFuncSetAttribute(tp_o3_kernel, cudaFuncAttributeMaxDynamicSharedMemorySize, SMEM_BYTES);
    cudaMemsetAsync(d_out, 0, (size_t)out_size * sizeof(float), 0);
    tp_o3_kernel<<<NROWS / TILE, NTHREADS, SMEM_BYTES>>>(x1, x2, wgt, out);
}

// round 4
// speedup vs baseline: 1.0028x; 1.0028x over previous
#include <cuda_runtime.h>
#include <cstdint>

// ---------------------------------------------------------------------------
// PureCartesianTensorProductO3: out[n,:] = sum over 15 paths x 4 parity combos
//   of  W_p[Z,a,b] * spatial_contract( t1[n,s1,L1,a,:], t2[n,s2,L2,b,:] )
// Layout per row (832 floats): s in {0,1} blocks of 416; within block
//   L0 at [0,32), L1 at [32,128), L2 at [128,416); element (c, spatial) at
//   c*3^L + lin(spatial).
// ---------------------------------------------------------------------------

#define NROWS   8192
#define FEAT    832
#define SBLK    416
#define TILE    16
#define NTHREADS 128

// path tables (compile-time)
__host__ __device__ constexpr int kP3[3]   = {1, 3, 9};
__host__ __device__ constexpr int kLOFF[3] = {0, 32, 128};
__host__ __device__ constexpr int kL1[15] = {0,0,0,1,1,1,1,1,1,2,2,2,2,2,2};
__host__ __device__ constexpr int kL2[15] = {0,1,2,0,1,1,1,2,2,0,1,1,2,2,2};
__host__ __device__ constexpr int kLO[15] = {0,1,2,1,2,0,1,1,2,2,1,2,2,0,1};
__host__ __device__ constexpr int kUE[15] = {0,0,0,0,0,0,1,0,1,0,0,1,0,0,1};

// SMEM carve (floats)
#define SX_STRIDE 833
#define SX_FLOATS (TILE * SX_STRIDE)              // 13328
#define SB_FLOATS (32 * 4 * 9 * TILE)             // 18432
#define SW_STRIDE 34
#define SW_FLOATS (128 * SW_STRIDE)               // 4352
#define SMEM_FLOATS (2 * SX_FLOATS + SB_FLOATS + SW_FLOATS)
#define SMEM_BYTES (SMEM_FLOATS * 4)              // 197760 B

typedef unsigned long long u64;

__device__ __forceinline__ u64 pk2(float x, float y) {
    u64 r; asm("mov.b64 %0, {%1, %2};" : "=l"(r) : "f"(x), "f"(y)); return r;
}
__device__ __forceinline__ void upk2(u64 v, float& x, float& y) {
    asm("mov.b64 {%0, %1}, %2;" : "=f"(x), "=f"(y) : "l"(v));
}
// packed 2x fp32 FMA (PTX-only on sm_103a; doubles FFMA throughput vs 3-reg FFMA)
__device__ __forceinline__ void ffma2(u64& d, u64 a, u64 b) {
    asm("fma.rn.f32x2 %0, %1, %2, %0;" : "+l"(d) : "l"(a), "l"(b));
}

__device__ __forceinline__ float dot3(const float* __restrict__ u, const float* __restrict__ v) {
    return fmaf(u[0], v[0], fmaf(u[1], v[1], u[2] * v[2]));
}
__device__ __forceinline__ void cross3(const float* __restrict__ u, const float* __restrict__ v,
                                       float* __restrict__ o) {
    o[0] = u[1] * v[2] - u[2] * v[1];
    o[1] = u[2] * v[0] - u[0] * v[2];
    o[2] = u[0] * v[1] - u[1] * v[0];
}

// Spatial contraction per path: B[m] from t1 (3^L1 floats) and t2 (3^L2 floats)
template <int P>
__device__ __forceinline__ void compute_B(const float* __restrict__ t1,
                                          const float* __restrict__ t2,
                                          float* __restrict__ B) {
    if constexpr (P == 0) {                // (0,0)->0
        B[0] = t1[0] * t2[0];
    } else if constexpr (P == 1) {         // (0,1)->1
        #pragma unroll
        for (int m = 0; m < 3; ++m) B[m] = t1[0] * t2[m];
    } else if constexpr (P == 2) {         // (0,2)->2
        #pragma unroll
        for (int m = 0; m < 9; ++m) B[m] = t1[0] * t2[m];
    } else if constexpr (P == 3) {         // (1,0)->1
        #pragma unroll
        for (int m = 0; m < 3; ++m) B[m] = t1[m] * t2[0];
    } else if constexpr (P == 4) {         // (1,1) k=0 ->2 : B[3i+j]=t1[i]t2[j]
        #pragma unroll
        for (int i = 0; i < 3; ++i)
            #pragma unroll
            for (int j = 0; j < 3; ++j) B[3 * i + j] = t1[i] * t2[j];
    } else if constexpr (P == 5) {         // (1,1) k=1 ->0 : dot
        B[0] = dot3(t1, t2);
    } else if constexpr (P == 6) {         // (1,1) eps ->1 : cross
        cross3(t1, t2, B);
    } else if constexpr (P == 7) {         // (1,2) k=1 ->1 : B[d]=sum_c t1[c]t2[d,c]
        #pragma unroll
        for (int d = 0; d < 3; ++d) B[d] = dot3(t1, t2 + 3 * d);
    } else if constexpr (P == 8) {         // (1,2) eps ->2 : B[d,p]=eps[p,c,e]t1[c]t2[d,e]
        #pragma unroll
        for (int d = 0; d < 3; ++d) cross3(t1, t2 + 3 * d, B + 3 * d);
    } else if constexpr (P == 9) {         // (2,0)->2
        #pragma unroll
        for (int m = 0; m < 9; ++m) B[m] = t1[m] * t2[0];
    } else if constexpr (P == 10) {        // (2,1) k=1 ->1 : B[c]=sum_d t1[c,d]t2[d]
        #pragma unroll
        for (int c = 0; c < 3; ++c) B[c] = dot3(t1 + 3 * c, t2);
    } else if constexpr (P == 11) {        // (2,1) eps ->2 : B[c,p]=eps[p,d,e]t1[c,d]t2[e]
        #pragma unroll
        for (int c = 0; c < 3; ++c) cross3(t1 + 3 * c, t2, B + 3 * c);
    } else if constexpr (P == 12) {        // (2,2) k=1 ->2 : B[c,e]=sum_d t1[c,d]t2[e,d]
        #pragma unroll
        for (int c = 0; c < 3; ++c)
            #pragma unroll
            for (int e = 0; e < 3; ++e) B[3 * c + e] = dot3(t1 + 3 * c, t2 + 3 * e);
    } else if constexpr (P == 13) {        // (2,2) k=2 ->0 : full dot
        float s = 0.f;
        #pragma unroll
        for (int i = 0; i < 9; ++i) s = fmaf(t1[i], t2[i], s);
        B[0] = s;
    } else {                               // P==14 (2,2) eps ->1 : B[p]=eps[p,c,e] M[c,e]
        float M01 = dot3(t1 + 0, t2 + 3), M02 = dot3(t1 + 0, t2 + 6);
        float M10 = dot3(t1 + 3, t2 + 0), M12 = dot3(t1 + 3, t2 + 6);
        float M20 = dot3(t1 + 6, t2 + 0), M21 = dot3(t1 + 6, t2 + 3);
        B[0] = M12 - M21;
        B[1] = M20 - M02;
        B[2] = M01 - M10;
    }
}

template <int P>
__device__ __forceinline__ void process_path(const float* __restrict__ wgt,
                                             float* __restrict__ out,
                                             const float* __restrict__ sx1,
                                             const float* __restrict__ sx2,
                                             float* __restrict__ sB,
                                             float* __restrict__ sW,
                                             int row0, int tid) {
    constexpr int L1 = kL1[P], L2 = kL2[P], Lo = kLO[P], UE = kUE[P];
    constexpr int d1 = kP3[L1], d2 = kP3[L2], Mout = kP3[Lo];
    constexpr int O1 = kLOFF[L1], O2 = kLOFF[L2], Oo = kLOFF[Lo];

    const int zp = tid & 15;   // Z-pair index: handles Z = 2*zp, 2*zp+1
    const int rp = tid >> 4;   // row-pair index: rows 2*rp, 2*rp+1

    #pragma unroll 1
    for (int ss = 0; ss < 4; ++ss) {
        const int s1 = ss >> 1, s2 = ss & 1;
        const int so = s1 ^ s2 ^ UE;
        const float* wb = wgt + (size_t)(P * 4 + ss) * 32768;

        u64 acc0[Mout], acc1[Mout];
        #pragma unroll
        for (int m = 0; m < Mout; ++m) { acc0[m] = 0ull; acc1[m] = 0ull; }

        #pragma unroll 1
        for (int a0 = 0; a0 < 32; a0 += 4) {
            __syncthreads();  // previous GEMM done reading sB/sW
            // ---- stage W slice: W[Z, a0 + (rem>>5), rem&31] -> sW[rem*34 + Z]
            #pragma unroll
            for (int it = 0; it < 32; ++it) {
                int i = tid + it * NTHREADS;
                int Z = i >> 7, rem = i & 127;
                sW[rem * SW_STRIDE + Z] = wb[Z * 1024 + a0 * 32 + rem];
            }
            // ---- stage B: slot index MUST match GEMM's rem = ac*32 + b
            #pragma unroll
            for (int it = 0; it < 16; ++it) {
                int e = tid + it * NTHREADS;
                int r = e & 15, slot = e >> 4;       // slot in [0,128)
                int ac = slot >> 5, b = slot & 31;   // slot == ac*32 + b
                const float* t1 = sx1 + r * SX_STRIDE + s1 * SBLK + O1 + (a0 + ac) * d1;
                const float* t2 = sx2 + r * SX_STRIDE + s2 * SBLK + O2 + b * d2;
                float Bm[Mout];
                compute_B<P>(t1, t2, Bm);
                #pragma unroll
                for (int m = 0; m < Mout; ++m) sB[(slot * Mout + m) * TILE + r] = Bm[m];
            }
            __syncthreads();
            // ---- rank-128 update, packed f32x2 over the row pair
            #pragma unroll 2
            for (int b = 0; b < 32; ++b) {
                #pragma unroll
                for (int ac = 0; ac < 4; ++ac) {
                    const int rem = ac * 32 + b;
                    float2 w2 = *reinterpret_cast<const float2*>(sW + rem * SW_STRIDE + 2 * zp);
                    u64 wA = pk2(w2.x, w2.x);  // Z = 2*zp
                    u64 wB = pk2(w2.y, w2.y);  // Z = 2*zp+1
                    const float* bp = sB + (size_t)rem * Mout * TILE + 2 * rp;
                    #pragma unroll
                    for (int m = 0; m < Mout; ++m) {
                        u64 bv = *reinterpret_cast<const u64*>(bp + m * TILE);
                        ffma2(acc0[m], wA, bv);
                        ffma2(acc1[m], wB, bv);
                    }
                }
            }
        }
        // ---- flush (global RMW; rows exclusive per block, locations exclusive per thread)
        const int ob = so * SBLK + Oo;
        float* o0 = out + (size_t)(row0 + 2 * rp) * FEAT;
        float* o1 = o0 + FEAT;
        #pragma unroll
        for (int m = 0; m < Mout; ++m) {
            float v00, v01, v10, v11;
            upk2(acc0[m], v00, v01);
            upk2(acc1[m], v10, v11);
            o0[ob + (2 * zp) * Mout + m]     += v00;
            o1[ob + (2 * zp) * Mout + m]     += v01;
            o0[ob + (2 * zp + 1) * Mout + m] += v10;
            o1[ob + (2 * zp + 1) * Mout + m] += v11;
        }
    }
}

__global__ __launch_bounds__(NTHREADS)
void tp_o3_kernel(const float* __restrict__ x1, const float* __restrict__ x2,
                  const float* __restrict__ wgt, float* __restrict__ out) {
    extern __shared__ float sm[];
    float* sx1 = sm;
    float* sx2 = sx1 + SX_FLOATS;
    float* sB  = sx2 + SX_FLOATS;
    float* sW  = sB + SB_FLOATS;

    const int tid  = threadIdx.x;
    const int row0 = blockIdx.x * TILE;

    // stage input tiles (padded stride for conflict-free scalar reads)
    #pragma unroll 4
    for (int i = tid; i < TILE * FEAT; i += NTHREADS) {
        int r = i / FEAT, f = i - r * FEAT;
        sx1[r * SX_STRIDE + f] = x1[(size_t)(row0 + r) * FEAT + f];
        sx2[r * SX_STRIDE + f] = x2[(size_t)(row0 + r) * FEAT + f];
    }
    // (first __syncthreads inside each process_path chunk loop orders the fill)

    process_path<0>(wgt, out, sx1, sx2, sB, sW, row0, tid);
    process_path<1>(wgt, out, sx1, sx2, sB, sW, row0, tid);
    process_path<2>(wgt, out, sx1, sx2, sB, sW, row0, tid);
    process_path<3>(wgt, out, sx1, sx2, sB, sW, row0, tid);
    process_path<4>(wgt, out, sx1, sx2, sB, sW, row0, tid);
    process_path<5>(wgt, out, sx1, sx2, sB, sW, row0, tid);
    process_path<6>(wgt, out, sx1, sx2, sB, sW, row0, tid);
    process_path<7>(wgt, out, sx1, sx2, sB, sW, row0, tid);
    process_path<8>(wgt, out, sx1, sx2, sB, sW, row0, tid);
    process_path<9>(wgt, out, sx1, sx2, sB, sW, row0, tid);
    process_path<10>(wgt, out, sx1, sx2, sB, sW, row0, tid);
    process_path<11>(wgt, out, sx1, sx2, sB, sW, row0, tid);
    process_path<12>(wgt, out, sx1, sx2, sB, sW, row0, tid);
    process_path<13>(wgt, out, sx1, sx2, sB, sW, row0, tid);
    process_path<14>(wgt, out, sx1, sx2, sB, sW, row0, tid);
}

extern "C" void kernel_launch(void* const* d_in, const int* in_sizes, int n_in,
                              void* d_out, int out_size) {
    const float* x1  = (const float*)d_in[0];
    const float* x2  = (const float*)d_in[1];
    const float* wgt = (const float*)d_in[2];
    float* out = (float*)d_out;

    cudaFuncSetAttribute(tp_o3_kernel, cudaFuncAttributeMaxDynamicSharedMemorySize, SMEM_BYTES);
    cudaMemsetAsync(d_out, 0, (size_t)out_size * sizeof(float), 0);
    tp_o3_kernel<<<NROWS / TILE, NTHREADS, SMEM_BYTES>>>(x1, x2, wgt, out);
}